// round 15
// baseline (speedup 1.0000x reference)
#include <cuda_runtime.h>
#include <cuda_bf16.h>

// SimpleLSS: softmax over depth sums to 1 -> weighted == img_feat.
// Whole op == bilinear upsample (24,256,16,44) -> (24,256,128,128),
// half-pixel centers, clamped edges. depth_logits never read.
//
// R15: champion R3 dataflow, 2 planes per CTA (grid 3072). Both planes'
// inputs preloaded up-front; halves per-byte prologue cost and cuts
// n_waves 5.2 -> 2.6 (wave transition ~2.4k cyc each, B300 model).
// Store path (.cs, float4, register-blocked vertical pass) unchanged.

#define IN_H 16
#define IN_W 44
#define OUT_HW 128
#define PLANE_IN (IN_H * IN_W)      // 704
#define PLANE_OUT (OUT_HW * OUT_HW) // 16384
#define PLANES_PER_CTA 2

__global__ __launch_bounds__(256) void lss_resize_kernel(
    const float* __restrict__ img, float* __restrict__ out)
{
    const int pbase = blockIdx.x * PLANES_PER_CTA;   // first plane of pair
    const float* __restrict__ src = img + (long long)pbase * PLANE_IN;

    __shared__ float tile[PLANES_PER_CTA * PLANE_IN];  // both raw inputs
    __shared__ float4 hrow[IN_H * 32];                 // 16 x 128 floats

    // ---- stage 0: preload both planes' inputs (1408 floats) ----
    #pragma unroll
    for (int i = threadIdx.x; i < PLANES_PER_CTA * PLANE_IN; i += 256)
        tile[i] = src[i];
    __syncthreads();

    const int c = threadIdx.x & 31;      // x-chunk index (stage 2)
    const int w = threadIdx.x >> 5;      // warp id 0..7
    const int x = c * 4;

    #pragma unroll
    for (int p = 0; p < PLANES_PER_CTA; ++p) {
        float* __restrict__ dst = out + (long long)(pbase + p) * PLANE_OUT;
        const float* tp = tile + p * PLANE_IN;

        // ---- stage 1: horizontal interp, 2048 values, 8/thread ----
        float* hrow_s = reinterpret_cast<float*>(hrow);
        #pragma unroll
        for (int k = 0; k < 8; ++k) {
            const int i = k * 256 + threadIdx.x;
            const int r = i >> 7;            // input row 0..15
            const int xo = i & 127;          // output col 0..127
            // horizontal scale 44/128 = 0.34375 (exact fp32)
            float sx = fmaxf(((float)xo + 0.5f) * 0.34375f - 0.5f, 0.0f);
            int   x0 = (int)sx;
            float fx = sx - (float)x0;
            int   x1 = min(x0 + 1, IN_W - 1);
            const float* rp = tp + r * IN_W;
            float v0 = rp[x0];
            hrow_s[i] = v0 + fx * (rp[x1] - v0);
        }
        __syncthreads();

        // ---- stage 2: vertical blend from registers ----
        // Warp layout: lane c owns x-chunk [4c,4c+3]; warp w handles row
        // groups g = w and g = w+8. Group g covers output rows 8g+4..8g+11
        // (fy = 0.0625 + 0.125*r); group 0 also emits rows 0-3 (fy = 0);
        // group 15's b clamps to hrow[15]; rows >= 128 skipped.
        #pragma unroll
        for (int s = 0; s < 2; ++s) {
            const int g = w + 8 * s;                         // 0..15
            float4 a = hrow[g * 32 + c];
            float4 b = hrow[min(g + 1, IN_H - 1) * 32 + c];
            float4 d;
            d.x = b.x - a.x; d.y = b.y - a.y;
            d.z = b.z - a.z; d.w = b.w - a.w;

            if (g == 0) {
                #pragma unroll
                for (int r = 0; r < 4; ++r)
                    __stcs(reinterpret_cast<float4*>(dst + r * OUT_HW + x), a);
            }

            #pragma unroll
            for (int r = 0; r < 8; ++r) {
                const int y = 8 * g + 4 + r;
                if (y < OUT_HW) {
                    const float fy = 0.0625f + 0.125f * (float)r;
                    float4 v;
                    v.x = a.x + fy * d.x;
                    v.y = a.y + fy * d.y;
                    v.z = a.z + fy * d.z;
                    v.w = a.w + fy * d.w;
                    __stcs(reinterpret_cast<float4*>(dst + y * OUT_HW + x), v);
                }
            }
        }
        // hrow reused next plane iteration; stores read only registers, but
        // stage 1 of plane p+1 rewrites hrow -> barrier needed.
        if (p + 1 < PLANES_PER_CTA) __syncthreads();
    }
}

extern "C" void kernel_launch(void* const* d_in, const int* in_sizes, int n_in,
                              void* d_out, int out_size)
{
    const float* img = (const float*)d_in[0];   // (24,256,16,44)
    float* out = (float*)d_out;                 // (24,256,128,128)
    const int planes = in_sizes[0] / PLANE_IN;  // 6144
    lss_resize_kernel<<<planes / PLANES_PER_CTA, 256>>>(img, out);
}

// round 16
// speedup vs baseline: 1.0153x; 1.0153x over previous
#include <cuda_runtime.h>
#include <cuda_bf16.h>

// SimpleLSS: softmax over depth sums to 1 -> weighted == img_feat.
// Whole op == bilinear upsample (24,256,16,44) -> (24,256,128,128),
// half-pixel centers, clamped edges. depth_logits never read.
//
// FINAL CHAMPION (R3 dataflow, 59.9us = HBM write floor):
//   separable interp, register-blocked vertical pass, .cs streaming stores.
//   403MB / 59.9us = 6.7 TB/s effective write stream.
// Exhaustively bounded:
//   - dataflows: monolithic 60.1 / register-blocked 59.9 / half-plane 60.2 /
//     TMA-staged 82.0 / plane-fused 61.5
//   - store width: v4 optimal; v8 regresses to 68us (L1tex wavefronts)
//   - store policy: .cs 60.0 / default 68.4 / .wt 68.4 (replay-state effect,
//     invisible to single-shot ncu)
//   - LDS/issue reductions (8x / 2x): zero dur effect — never binding.

#define IN_H 16
#define IN_W 44
#define OUT_HW 128
#define PLANE_IN (IN_H * IN_W)      // 704
#define PLANE_OUT (OUT_HW * OUT_HW) // 16384

__global__ __launch_bounds__(256) void lss_resize_kernel(
    const float* __restrict__ img, float* __restrict__ out)
{
    const int plane = blockIdx.x;                 // n*256 + c
    const float* __restrict__ src = img + (long long)plane * PLANE_IN;
    float* __restrict__ dst = out + (long long)plane * PLANE_OUT;

    __shared__ float tile[PLANE_IN];          // raw 16x44 input
    __shared__ float4 hrow[IN_H * 32];        // 16 rows x 128 floats (as float4)

    // ---- load input plane (704 floats) ----
    for (int i = threadIdx.x; i < PLANE_IN; i += 256)
        tile[i] = src[i];
    __syncthreads();

    // ---- stage 1: horizontal interp, 16*128 = 2048 values, 8/thread ----
    float* hrow_s = reinterpret_cast<float*>(hrow);
    #pragma unroll
    for (int k = 0; k < 8; ++k) {
        const int i = k * 256 + threadIdx.x;
        const int r = i >> 7;            // input row 0..15
        const int x = i & 127;           // output col 0..127
        // horizontal scale 44/128 = 0.34375 (exact fp32)
        float sx = fmaxf(((float)x + 0.5f) * 0.34375f - 0.5f, 0.0f);
        int   x0 = (int)sx;
        float fx = sx - (float)x0;
        int   x1 = min(x0 + 1, IN_W - 1);
        const float* rp = tile + r * IN_W;
        float v0 = rp[x0];
        hrow_s[i] = v0 + fx * (rp[x1] - v0);
    }
    __syncthreads();

    // ---- stage 2: vertical blend from registers ----
    // Warp layout: lane c owns x-chunk [4c, 4c+3]; warp w handles row
    // groups g = w and g = w+8. Group g covers output rows 8g+4..8g+11
    // (fy = 0.0625 + 0.125*r); group 0 also emits rows 0-3 (fy = 0);
    // group 15's b clamps to hrow[15] (delta = 0); rows >= 128 skipped.
    const int c = threadIdx.x & 31;      // x-chunk index
    const int w = threadIdx.x >> 5;      // warp id 0..7
    const int x = c * 4;

    #pragma unroll
    for (int s = 0; s < 2; ++s) {
        const int g = w + 8 * s;                         // 0..15
        float4 a = hrow[g * 32 + c];
        float4 b = hrow[min(g + 1, IN_H - 1) * 32 + c];
        float4 d;
        d.x = b.x - a.x; d.y = b.y - a.y;
        d.z = b.z - a.z; d.w = b.w - a.w;

        if (g == 0) {
            #pragma unroll
            for (int r = 0; r < 4; ++r)
                __stcs(reinterpret_cast<float4*>(dst + r * OUT_HW + x), a);
        }

        #pragma unroll
        for (int r = 0; r < 8; ++r) {
            const int y = 8 * g + 4 + r;
            if (y < OUT_HW) {
                const float fy = 0.0625f + 0.125f * (float)r;
                float4 v;
                v.x = a.x + fy * d.x;
                v.y = a.y + fy * d.y;
                v.z = a.z + fy * d.z;
                v.w = a.w + fy * d.w;
                __stcs(reinterpret_cast<float4*>(dst + y * OUT_HW + x), v);
            }
        }
    }
}

extern "C" void kernel_launch(void* const* d_in, const int* in_sizes, int n_in,
                              void* d_out, int out_size)
{
    const float* img = (const float*)d_in[0];   // (24,256,16,44)
    float* out = (float*)d_out;                 // (24,256,128,128)
    const int planes = in_sizes[0] / PLANE_IN;  // 6144
    lss_resize_kernel<<<planes, 256>>>(img, out);
}